// round 8
// baseline (speedup 1.0000x reference)
#include <cuda_runtime.h>
#include <cstdint>

// Problem constants
#define SQ   2048          // sequence length
#define DM   1024          // model dim
#define NH   16            // heads
#define HD   64            // head dim
#define NB   2             // batch
#define MT   (NB*SQ)       // 4096 rows total

// Scratch (device globals; no allocation allowed in kernel_launch)
__device__ float g_Q[NB*NH*SQ*HD];   // [B,H,S,HD]
__device__ float g_K[NB*NH*SQ*HD];
__device__ float g_V[NB*NH*SQ*HD];
__device__ float g_O[MT*DM];         // [B,S,D] attention output (pre out-proj)

// ---------------------------------------------------------------------------
// helpers
// ---------------------------------------------------------------------------
__device__ __forceinline__ uint32_t f2tf(float f) {
    uint32_t u;
    asm("cvt.rna.tf32.f32 %0, %1;" : "=r"(u) : "f"(f));
    return u;
}

__device__ __forceinline__ void mma8(float& c0, float& c1, float& c2, float& c3,
                                     uint32_t a0, uint32_t a1, uint32_t a2, uint32_t a3,
                                     uint32_t b0, uint32_t b1) {
    asm("mma.sync.aligned.m16n8k8.row.col.f32.tf32.tf32.f32 "
        "{%0,%1,%2,%3}, {%4,%5,%6,%7}, {%8,%9}, {%0,%1,%2,%3};"
        : "+f"(c0), "+f"(c1), "+f"(c2), "+f"(c3)
        : "r"(a0), "r"(a1), "r"(a2), "r"(a3), "r"(b0), "r"(b1));
}

// ldmatrix x4: four 8x4 b32 tiles; lane l gets, per tile, element (l>>2, l&3).
__device__ __forceinline__ void ldsm4(uint32_t& r0, uint32_t& r1,
                                      uint32_t& r2, uint32_t& r3, uint32_t addr) {
    asm volatile("ldmatrix.sync.aligned.m8n8.x4.shared.b16 {%0,%1,%2,%3}, [%4];"
                 : "=r"(r0), "=r"(r1), "=r"(r2), "=r"(r3) : "r"(addr));
}

__device__ __forceinline__ uint32_t smem_u32(const void* p) {
    return (uint32_t)__cvta_generic_to_shared(p);
}

// ---------------------------------------------------------------------------
// tf32 tensor-core GEMM: C = A[M,K] @ W[N,K]^T + bias[N]
//   MODE 0: C row-major [M,N]      (launched gridDim.z = 1)
//   MODE 1: C head-split           (launched gridDim.z = 3: fused Q/K/V)
// 128x128 block, BK=32, 8 warps (2Mx4N), warp tile 64x32, ldmatrix fragments,
// DOUBLE-BUFFERED smem: one sync per k-tile, staging overlapped with compute.
// ---------------------------------------------------------------------------
#define SMS 36                        // smem row stride in floats
#define GEMM_BUF (128*SMS)            // uint32 per array per buffer
#define GEMM_SMEM (4*GEMM_BUF*4)      // bytes: A(x2) + B(x2)

template<int MODE>
__global__ void __launch_bounds__(256, 1)
gemm_tc_kernel(const float* A0, const float* A1, const float* A2,
               const float* W0, const float* W1, const float* W2,
               const float* bi0, const float* bi1, const float* bi2,
               float* C0, float* C1, float* C2)
{
    extern __shared__ uint32_t gsm[];
    uint32_t* As = gsm;                  // [2][GEMM_BUF]
    uint32_t* Bs = gsm + 2 * GEMM_BUF;   // [2][GEMM_BUF]

    const int z = blockIdx.z;
    const float* A    = (z == 0) ? A0  : (z == 1) ? A1  : A2;
    const float* W    = (z == 0) ? W0  : (z == 1) ? W1  : W2;
    const float* bias = (z == 0) ? bi0 : (z == 1) ? bi1 : bi2;
    float*       C    = (z == 0) ? C0  : (z == 1) ? C1  : C2;

    const int tid  = threadIdx.x;
    const int lane = tid & 31;
    const int wid  = tid >> 5;
    const int wm   = wid >> 2;        // 0..1  (M warp)
    const int wn   = wid & 3;         // 0..3  (N warp)
    const int lr   = lane >> 2;       // 0..7
    const int lk   = lane & 3;        // 0..3
    const int seg  = lane >> 3;       // ldmatrix tile segment 0..3
    const int sr   = lane & 7;        // row within tile segment
    const int bm   = blockIdx.y * 128;
    const int bn   = blockIdx.x * 128;

    const int grow = tid >> 3;        // base row (0..31), +32 per i
    const int gf4  = tid & 7;         // float4 index within 32-float k-chunk

    // ldmatrix per-lane base addresses (bytes) in buffer 0.
    uint32_t aab[4];
    const uint32_t asBase = smem_u32(As);
    #pragma unroll
    for (int mt = 0; mt < 4; mt++)
        aab[mt] = asBase + (((wm * 64 + mt * 16 + (seg & 1) * 8 + sr) * SMS
                             + (seg >> 1) * 4) << 2);
    uint32_t bab[2];
    const uint32_t bsBase = smem_u32(Bs);
    #pragma unroll
    for (int p = 0; p < 2; p++)
        bab[p] = bsBase + (((wn * 32 + p * 16 + (seg >> 1) * 8 + sr) * SMS
                            + (seg & 1) * 4) << 2);

    float acc[4][4][4];
    #pragma unroll
    for (int mt = 0; mt < 4; mt++)
        #pragma unroll
        for (int nt = 0; nt < 4; nt++)
            #pragma unroll
            for (int r = 0; r < 4; r++) acc[mt][nt][r] = 0.f;

    float4 pa[4], pb[4];

    // prefetch tile 0 and stage into buffer 0
    #pragma unroll
    for (int i = 0; i < 4; i++) {
        const int row = grow + i * 32;
        pa[i] = *(const float4*)(A + (size_t)(bm + row) * DM + gf4 * 4);
        pb[i] = *(const float4*)(W + (size_t)(bn + row) * DM + gf4 * 4);
    }
    #pragma unroll
    for (int i = 0; i < 4; i++) {
        const int row = grow + i * 32;
        *(uint4*)&As[row * SMS + gf4 * 4] =
            make_uint4(f2tf(pa[i].x), f2tf(pa[i].y), f2tf(pa[i].z), f2tf(pa[i].w));
        *(uint4*)&Bs[row * SMS + gf4 * 4] =
            make_uint4(f2tf(pb[i].x), f2tf(pb[i].y), f2tf(pb[i].z), f2tf(pb[i].w));
    }
    __syncthreads();

    const int NT = DM / 32;
    for (int t = 0; t < NT; t++) {
        const uint32_t bo = (uint32_t)(t & 1) * (GEMM_BUF * 4);   // ldmatrix byte offset
        const int nb = (t + 1) & 1;

        // issue global loads for next tile (covered by compute below)
        if (t + 1 < NT) {
            const int k0 = (t + 1) * 32;
            #pragma unroll
            for (int i = 0; i < 4; i++) {
                const int row = grow + i * 32;
                pa[i] = *(const float4*)(A + (size_t)(bm + row) * DM + k0 + gf4 * 4);
                pb[i] = *(const float4*)(W + (size_t)(bn + row) * DM + k0 + gf4 * 4);
            }
        }

        // compute current tile
        #pragma unroll
        for (int kk = 0; kk < 4; kk++) {
            const uint32_t koff = bo + kk * 32;
            uint32_t af[4][4], bf[4][2];
            #pragma unroll
            for (int mt = 0; mt < 4; mt++)
                ldsm4(af[mt][0], af[mt][1], af[mt][2], af[mt][3], aab[mt] + koff);
            ldsm4(bf[0][0], bf[0][1], bf[1][0], bf[1][1], bab[0] + koff);
            ldsm4(bf[2][0], bf[2][1], bf[3][0], bf[3][1], bab[1] + koff);
            #pragma unroll
            for (int mt = 0; mt < 4; mt++)
                #pragma unroll
                for (int nt = 0; nt < 4; nt++)
                    mma8(acc[mt][nt][0], acc[mt][nt][1], acc[mt][nt][2], acc[mt][nt][3],
                         af[mt][0], af[mt][1], af[mt][2], af[mt][3],
                         bf[nt][0], bf[nt][1]);
        }

        // stage next tile into the other buffer
        if (t + 1 < NT) {
            uint32_t* Ad = As + nb * GEMM_BUF;
            uint32_t* Bd = Bs + nb * GEMM_BUF;
            #pragma unroll
            for (int i = 0; i < 4; i++) {
                const int row = grow + i * 32;
                *(uint4*)&Ad[row * SMS + gf4 * 4] =
                    make_uint4(f2tf(pa[i].x), f2tf(pa[i].y), f2tf(pa[i].z), f2tf(pa[i].w));
                *(uint4*)&Bd[row * SMS + gf4 * 4] =
                    make_uint4(f2tf(pb[i].x), f2tf(pb[i].y), f2tf(pb[i].z), f2tf(pb[i].w));
            }
        }
        __syncthreads();
    }

    // Epilogue
    #pragma unroll
    for (int mt = 0; mt < 4; mt++) {
        const int row = bm + wm * 64 + mt * 16 + lr;
        #pragma unroll
        for (int nt = 0; nt < 4; nt++) {
            const int col = bn + wn * 32 + nt * 8 + 2 * lk;
            const float bx = bias[col];
            const float by = bias[col + 1];
            float2 r0 = make_float2(acc[mt][nt][0] + bx, acc[mt][nt][1] + by);
            float2 r1 = make_float2(acc[mt][nt][2] + bx, acc[mt][nt][3] + by);
            if (MODE == 0) {
                *(float2*)&C[(size_t)row * DM + col]       = r0;
                *(float2*)&C[(size_t)(row + 8) * DM + col] = r1;
            } else {
                const int h_  = col >> 6;
                const int dk  = col & (HD - 1);
                const int b0_ = row >> 11;
                const int s0_ = row & (SQ - 1);
                const int b1_ = (row + 8) >> 11;
                const int s1_ = (row + 8) & (SQ - 1);
                *(float2*)&C[(((size_t)(b0_ * NH + h_) * SQ) + s0_) * HD + dk] = r0;
                *(float2*)&C[(((size_t)(b1_ * NH + h_) * SQ) + s1_) * HD + dk] = r1;
            }
        }
    }
}

// ---------------------------------------------------------------------------
// Tensor-core flash attention (causal), tf32 mma, DOUBLE-BUFFERED K/V smem.
// QK^T split: qh*kh + qh*kl (K residual-compensated).
// Block = 128 q-rows of one (b,h); 8 warps; key tiles of 64.
// ---------------------------------------------------------------------------
#define KST 68                        // K smem row stride (floats)
#define VST 72                        // V smem row stride (floats)
#define ABUF (64*KST*2 + 64*VST)      // uint32 per buffer
#define ATTN_SMEM (2*ABUF*4)          // bytes

__global__ void __launch_bounds__(256, 1)
attn_tc_kernel(const float* __restrict__ Q, const float* __restrict__ K,
               const float* __restrict__ V, float* __restrict__ O)
{
    extern __shared__ uint32_t smem[];   // [2][ Kh(64*KST) | Kl(64*KST) | Vs(64*VST) ]

    const int tid  = threadIdx.x;
    const int lane = tid & 31;
    const int w    = tid >> 5;           // warp 0..7
    const int lr   = lane >> 2;          // group id 0..7
    const int lk   = lane & 3;           // thread-in-group 0..3
    const int seg  = lane >> 3;
    const int sr   = lane & 7;

    const int qblk = (SQ / 128 - 1) - blockIdx.x;   // reversed: long blocks first
    const int h    = blockIdx.y;
    const int b    = blockIdx.z;
    const int qbase = qblk * 128;

    const size_t headbase = (size_t)(b * NH + h) * SQ * HD;
    const float* Qg = Q + headbase;
    const float* Kg = K + headbase;
    const float* Vg = V + headbase;

    // ldmatrix per-lane base addrs for K tiles (buffer 0)
    uint32_t khb[4], klb[4];
    {
        const uint32_t sBase = smem_u32(smem);
        #pragma unroll
        for (int p = 0; p < 4; p++) {
            const uint32_t off = (((p * 16 + (seg >> 1) * 8 + sr) * KST
                                   + (seg & 1) * 4) << 2);
            khb[p] = sBase + off;
            klb[p] = sBase + (64 * KST * 4) + off;
        }
    }

    // --- Q fragments (persistent, single tf32), rows w*16 + {lr, lr+8} ---
    const int r0 = qbase + w * 16 + lr;
    uint32_t qh[8][4];
    #pragma unroll
    for (int kk = 0; kk < 8; kk++) {
        qh[kk][0] = f2tf(Qg[(size_t)r0 * HD + kk * 8 + lk]);
        qh[kk][1] = f2tf(Qg[(size_t)(r0 + 8) * HD + kk * 8 + lk]);
        qh[kk][2] = f2tf(Qg[(size_t)r0 * HD + kk * 8 + 4 + lk]);
        qh[kk][3] = f2tf(Qg[(size_t)(r0 + 8) * HD + kk * 8 + 4 + lk]);
    }

    float oacc[8][4];
    #pragma unroll
    for (int nt = 0; nt < 8; nt++)
        #pragma unroll
        for (int r = 0; r < 4; r++) oacc[nt][r] = 0.f;

    float m0 = -1e30f, m1 = -1e30f, l0 = 0.f, l1 = 0.f;

    const int ntiles = 2 * qblk + 2;

    // staging slot for this thread
    const int strow = tid >> 4;          // +16 per i
    const int stc4  = (tid & 15) * 4;

    // prefetch tile 0 into registers, stage into buffer 0
    float4 pk[4], pv[4];
    #pragma unroll
    for (int i = 0; i < 4; i++) {
        const int row = strow + i * 16;
        pk[i] = *(const float4*)&Kg[(size_t)row * HD + stc4];
        pv[i] = *(const float4*)&Vg[(size_t)row * HD + stc4];
    }
    {
        uint32_t* Kh0 = smem;
        uint32_t* Kl0 = smem + 64 * KST;
        uint32_t* Vs0 = smem + 64 * KST * 2;
        #pragma unroll
        for (int i = 0; i < 4; i++) {
            const int row = strow + i * 16;
            uint32_t hx = f2tf(pk[i].x), hy = f2tf(pk[i].y),
                     hz = f2tf(pk[i].z), hw = f2tf(pk[i].w);
            *(uint4*)&Kh0[row * KST + stc4] = make_uint4(hx, hy, hz, hw);
            *(uint4*)&Kl0[row * KST + stc4] = make_uint4(
                f2tf(pk[i].x - __uint_as_float(hx)), f2tf(pk[i].y - __uint_as_float(hy)),
                f2tf(pk[i].z - __uint_as_float(hz)), f2tf(pk[i].w - __uint_as_float(hw)));
            *(uint4*)&Vs0[row * VST + stc4] = make_uint4(f2tf(pv[i].x), f2tf(pv[i].y),
                                                         f2tf(pv[i].z), f2tf(pv[i].w));
        }
    }
    __syncthreads();

    for (int kt = 0; kt < ntiles; kt++) {
        const uint32_t bo = (uint32_t)(kt & 1) * (ABUF * 4);
        const uint32_t* Vsb = smem + (kt & 1) * ABUF + 64 * KST * 2;
        const int nb = (kt + 1) & 1;

        // issue global loads for next tile
        if (kt + 1 < ntiles) {
            #pragma unroll
            for (int i = 0; i < 4; i++) {
                const int row = (kt + 1) * 64 + strow + i * 16;
                pk[i] = *(const float4*)&Kg[(size_t)row * HD + stc4];
                pv[i] = *(const float4*)&Vg[(size_t)row * HD + stc4];
            }
        }

        // --- S = Q K^T (qh*kh + qh*kl) ---
        float sacc[8][4];
        #pragma unroll
        for (int nt = 0; nt < 8; nt++)
            #pragma unroll
            for (int r = 0; r < 4; r++) sacc[nt][r] = 0.f;

        #pragma unroll
        for (int kk = 0; kk < 8; kk++) {
            const uint32_t koff = bo + kk * 32;
            uint32_t kb[8][2], lb[8][2];
            #pragma unroll
            for (int p = 0; p < 4; p++) {
                ldsm4(kb[2*p][0], kb[2*p][1], kb[2*p+1][0], kb[2*p+1][1], khb[p] + koff);
                ldsm4(lb[2*p][0], lb[2*p][1], lb[2*p+1][0], lb[2*p+1][1], klb[p] + koff);
            }
            #pragma unroll
            for (int nt = 0; nt < 8; nt++) {
                mma8(sacc[nt][0], sacc[nt][1], sacc[nt][2], sacc[nt][3],
                     qh[kk][0], qh[kk][1], qh[kk][2], qh[kk][3], kb[nt][0], kb[nt][1]);
                mma8(sacc[nt][0], sacc[nt][1], sacc[nt][2], sacc[nt][3],
                     qh[kk][0], qh[kk][1], qh[kk][2], qh[kk][3], lb[nt][0], lb[nt][1]);
            }
        }

        // --- scale + causal mask ---
        const bool may_mask = (kt * 64 + 63 > qbase);
        #pragma unroll
        for (int nt = 0; nt < 8; nt++) {
            const int c = kt * 64 + nt * 8 + 2 * lk;
            #pragma unroll
            for (int r = 0; r < 4; r++) sacc[nt][r] *= 0.125f;
            if (may_mask) {
                if (c     > r0)     sacc[nt][0] = -1e30f;
                if (c + 1 > r0)     sacc[nt][1] = -1e30f;
                if (c     > r0 + 8) sacc[nt][2] = -1e30f;
                if (c + 1 > r0 + 8) sacc[nt][3] = -1e30f;
            }
        }

        // --- online softmax (rows r0 and r0+8) ---
        float tm0 = -1e30f, tm1 = -1e30f;
        #pragma unroll
        for (int nt = 0; nt < 8; nt++) {
            tm0 = fmaxf(tm0, fmaxf(sacc[nt][0], sacc[nt][1]));
            tm1 = fmaxf(tm1, fmaxf(sacc[nt][2], sacc[nt][3]));
        }
        tm0 = fmaxf(tm0, __shfl_xor_sync(0xffffffff, tm0, 1));
        tm0 = fmaxf(tm0, __shfl_xor_sync(0xffffffff, tm0, 2));
        tm1 = fmaxf(tm1, __shfl_xor_sync(0xffffffff, tm1, 1));
        tm1 = fmaxf(tm1, __shfl_xor_sync(0xffffffff, tm1, 2));

        const float mn0 = fmaxf(m0, tm0);
        const float mn1 = fmaxf(m1, tm1);
        const float cor0 = __expf(m0 - mn0);
        const float cor1 = __expf(m1 - mn1);
        m0 = mn0; m1 = mn1;

        float sum0 = 0.f, sum1 = 0.f;
        #pragma unroll
        for (int nt = 0; nt < 8; nt++) {
            sacc[nt][0] = __expf(sacc[nt][0] - m0);
            sacc[nt][1] = __expf(sacc[nt][1] - m0);
            sacc[nt][2] = __expf(sacc[nt][2] - m1);
            sacc[nt][3] = __expf(sacc[nt][3] - m1);
            sum0 += sacc[nt][0] + sacc[nt][1];
            sum1 += sacc[nt][2] + sacc[nt][3];
        }
        sum0 += __shfl_xor_sync(0xffffffff, sum0, 1);
        sum0 += __shfl_xor_sync(0xffffffff, sum0, 2);
        sum1 += __shfl_xor_sync(0xffffffff, sum1, 1);
        sum1 += __shfl_xor_sync(0xffffffff, sum1, 2);
        l0 = l0 * cor0 + sum0;
        l1 = l1 * cor1 + sum1;

        #pragma unroll
        for (int nt = 0; nt < 8; nt++) {
            oacc[nt][0] *= cor0; oacc[nt][1] *= cor0;
            oacc[nt][2] *= cor1; oacc[nt][3] *= cor1;
        }

        // --- O += P V ---
        const int s0 = (lane & ~3) | (lk >> 1);   // src lane for cols lk
        const int s2 = s0 + 2;                    // src lane for cols lk+4
        const int par = lk & 1;
        #pragma unroll
        for (int kk = 0; kk < 8; kk++) {
            float v00 = __shfl_sync(0xffffffff, sacc[kk][0], s0);
            float v01 = __shfl_sync(0xffffffff, sacc[kk][1], s0);
            float v20 = __shfl_sync(0xffffffff, sacc[kk][0], s2);
            float v21 = __shfl_sync(0xffffffff, sacc[kk][1], s2);
            float v10 = __shfl_sync(0xffffffff, sacc[kk][2], s0);
            float v11 = __shfl_sync(0xffffffff, sacc[kk][3], s0);
            float v30 = __shfl_sync(0xffffffff, sacc[kk][2], s2);
            float v31 = __shfl_sync(0xffffffff, sacc[kk][3], s2);
            uint32_t a0 = f2tf(par ? v01 : v00);
            uint32_t a1 = f2tf(par ? v11 : v10);
            uint32_t a2 = f2tf(par ? v21 : v20);
            uint32_t a3 = f2tf(par ? v31 : v30);

            #pragma unroll
            for (int nt = 0; nt < 8; nt++) {
                uint32_t vb0 = Vsb[(kk * 8 + lk) * VST + nt * 8 + lr];
                uint32_t vb1 = Vsb[(kk * 8 + 4 + lk) * VST + nt * 8 + lr];
                mma8(oacc[nt][0], oacc[nt][1], oacc[nt][2], oacc[nt][3],
                     a0, a1, a2, a3, vb0, vb1);
            }
        }

        // stage next tile into the other buffer
        if (kt + 1 < ntiles) {
            uint32_t* Khd = smem + nb * ABUF;
            uint32_t* Kld = Khd + 64 * KST;
            uint32_t* Vsd = Khd + 64 * KST * 2;
            #pragma unroll
            for (int i = 0; i < 4; i++) {
                const int row = strow + i * 16;
                uint32_t hx = f2tf(pk[i].x), hy = f2tf(pk[i].y),
                         hz = f2tf(pk[i].z), hw = f2tf(pk[i].w);
                *(uint4*)&Khd[row * KST + stc4] = make_uint4(hx, hy, hz, hw);
                *(uint4*)&Kld[row * KST + stc4] = make_uint4(
                    f2tf(pk[i].x - __uint_as_float(hx)), f2tf(pk[i].y - __uint_as_float(hy)),
                    f2tf(pk[i].z - __uint_as_float(hz)), f2tf(pk[i].w - __uint_as_float(hw)));
                *(uint4*)&Vsd[row * VST + stc4] = make_uint4(f2tf(pv[i].x), f2tf(pv[i].y),
                                                             f2tf(pv[i].z), f2tf(pv[i].w));
            }
        }
        __syncthreads();
    }

    // --- write O: [b, s, h*64 + d] ---
    const float inv0 = 1.f / l0;
    const float inv1 = 1.f / l1;
    float* Ob0 = O + ((size_t)b * SQ + r0) * DM + h * HD;
    float* Ob1 = O + ((size_t)b * SQ + r0 + 8) * DM + h * HD;
    #pragma unroll
    for (int nt = 0; nt < 8; nt++) {
        const int c = nt * 8 + 2 * lk;
        *(float2*)&Ob0[c] = make_float2(oacc[nt][0] * inv0, oacc[nt][1] * inv0);
        *(float2*)&Ob1[c] = make_float2(oacc[nt][2] * inv1, oacc[nt][3] * inv1);
    }
}

// ---------------------------------------------------------------------------
// Launch: fused QKV projection GEMM -> TC flash attention -> output GEMM
// Inputs (metadata order): query, key, value, mask(unused; tril causal),
//   w_q, b_q, w_k, b_k, w_v, b_v, w_out, b_out
// ---------------------------------------------------------------------------
extern "C" void kernel_launch(void* const* d_in, const int* in_sizes, int n_in,
                              void* d_out, int out_size)
{
    const float* query = (const float*)d_in[0];
    const float* key   = (const float*)d_in[1];
    const float* value = (const float*)d_in[2];
    const float* w_q   = (const float*)d_in[4];
    const float* b_q   = (const float*)d_in[5];
    const float* w_k   = (const float*)d_in[6];
    const float* b_k   = (const float*)d_in[7];
    const float* w_v   = (const float*)d_in[8];
    const float* b_v   = (const float*)d_in[9];
    const float* w_out = (const float*)d_in[10];
    const float* b_out = (const float*)d_in[11];

    float *Qp, *Kp, *Vp, *Op;
    cudaGetSymbolAddress((void**)&Qp, g_Q);
    cudaGetSymbolAddress((void**)&Kp, g_K);
    cudaGetSymbolAddress((void**)&Vp, g_V);
    cudaGetSymbolAddress((void**)&Op, g_O);

    cudaFuncSetAttribute(gemm_tc_kernel<1>,
                         cudaFuncAttributeMaxDynamicSharedMemorySize, GEMM_SMEM);
    cudaFuncSetAttribute(gemm_tc_kernel<0>,
                         cudaFuncAttributeMaxDynamicSharedMemorySize, GEMM_SMEM);
    cudaFuncSetAttribute(attn_tc_kernel,
                         cudaFuncAttributeMaxDynamicSharedMemorySize, ATTN_SMEM);

    // fused Q/K/V projections: gridDim.z selects operand set
    dim3 pgrid(DM / 128, MT / 128, 3);   // (8, 32, 3)
    gemm_tc_kernel<1><<<pgrid, 256, GEMM_SMEM>>>(
        query, key, value, w_q, w_k, w_v, b_q, b_k, b_v, Qp, Kp, Vp);

    attn_tc_kernel<<<dim3(SQ / 128, NH, NB), 256, ATTN_SMEM>>>(Qp, Kp, Vp, Op);

    dim3 ogrid(DM / 128, MT / 128, 1);
    gemm_tc_kernel<0><<<ogrid, 256, GEMM_SMEM>>>(
        Op, Op, Op, w_out, w_out, w_out, b_out, b_out, b_out,
        (float*)d_out, (float*)d_out, (float*)d_out);
}

// round 10
// speedup vs baseline: 1.5679x; 1.5679x over previous
#include <cuda_runtime.h>
#include <cstdint>

// Problem constants
#define SQ   2048          // sequence length
#define DM   1024          // model dim
#define NH   16            // heads
#define HD   64            // head dim
#define NB   2             // batch
#define MT   (NB*SQ)       // 4096 rows total

// Scratch (device globals; no allocation allowed in kernel_launch)
__device__ float g_Q[NB*NH*SQ*HD];   // [B,H,S,HD]
__device__ float g_K[NB*NH*SQ*HD];
__device__ float g_V[NB*NH*SQ*HD];
__device__ float g_O[MT*DM];         // [B,S,D] attention output (pre out-proj)

// ---------------------------------------------------------------------------
// helpers
// ---------------------------------------------------------------------------
__device__ __forceinline__ uint32_t f2tf(float f) {
    uint32_t u;
    asm("cvt.rna.tf32.f32 %0, %1;" : "=r"(u) : "f"(f));
    return u;
}

__device__ __forceinline__ float ex2f(float x) {
    float r;
    asm("ex2.approx.ftz.f32 %0, %1;" : "=f"(r) : "f"(x));
    return r;
}

__device__ __forceinline__ void mma8(float& c0, float& c1, float& c2, float& c3,
                                     uint32_t a0, uint32_t a1, uint32_t a2, uint32_t a3,
                                     uint32_t b0, uint32_t b1) {
    asm("mma.sync.aligned.m16n8k8.row.col.f32.tf32.tf32.f32 "
        "{%0,%1,%2,%3}, {%4,%5,%6,%7}, {%8,%9}, {%0,%1,%2,%3};"
        : "+f"(c0), "+f"(c1), "+f"(c2), "+f"(c3)
        : "r"(a0), "r"(a1), "r"(a2), "r"(a3), "r"(b0), "r"(b1));
}

// ldmatrix x4: four 8x4 b32 tiles; lane l gets, per tile, element (l>>2, l&3).
__device__ __forceinline__ void ldsm4(uint32_t& r0, uint32_t& r1,
                                      uint32_t& r2, uint32_t& r3, uint32_t addr) {
    asm volatile("ldmatrix.sync.aligned.m8n8.x4.shared.b16 {%0,%1,%2,%3}, [%4];"
                 : "=r"(r0), "=r"(r1), "=r"(r2), "=r"(r3) : "r"(addr));
}

__device__ __forceinline__ uint32_t smem_u32(const void* p) {
    return (uint32_t)__cvta_generic_to_shared(p);
}

// ---------------------------------------------------------------------------
// tf32 tensor-core GEMM (R7 two-sync structure): C = A[M,K]@W[N,K]^T + bias
//   MODE 0: C row-major [M,N]     (launched gridDim.z = 1)
//   MODE 1: C head-split          (launched gridDim.z = 3: fused Q/K/V)
// 128x128 block, BK=32, 8 warps (2Mx4N), warp tile 64x32, ldmatrix fragments.
// ---------------------------------------------------------------------------
#define SMS 36   // smem row stride in floats (4*row+k bijective mod 32)

template<int MODE>
__global__ void __launch_bounds__(256, 1)
gemm_tc_kernel(const float* A0, const float* A1, const float* A2,
               const float* W0, const float* W1, const float* W2,
               const float* bi0, const float* bi1, const float* bi2,
               float* C0, float* C1, float* C2)
{
    __shared__ uint32_t As[128 * SMS];
    __shared__ uint32_t Bs[128 * SMS];

    const int z = blockIdx.z;
    const float* A    = (z == 0) ? A0  : (z == 1) ? A1  : A2;
    const float* W    = (z == 0) ? W0  : (z == 1) ? W1  : W2;
    const float* bias = (z == 0) ? bi0 : (z == 1) ? bi1 : bi2;
    float*       C    = (z == 0) ? C0  : (z == 1) ? C1  : C2;

    const int tid  = threadIdx.x;
    const int lane = tid & 31;
    const int wid  = tid >> 5;
    const int wm   = wid >> 2;        // 0..1  (M warp)
    const int wn   = wid & 3;         // 0..3  (N warp)
    const int lr   = lane >> 2;       // 0..7
    const int lk   = lane & 3;        // 0..3
    const int seg  = lane >> 3;       // ldmatrix tile segment 0..3
    const int sr   = lane & 7;        // row within tile segment
    const int bm   = blockIdx.y * 128;
    const int bn   = blockIdx.x * 128;

    const int grow = tid >> 3;        // base row (0..31), +32 per i
    const int gf4  = tid & 7;         // float4 index within 32-float k-chunk

    // ldmatrix per-lane base addresses (bytes)
    uint32_t aab[4];
    const uint32_t asBase = smem_u32(As);
    #pragma unroll
    for (int mt = 0; mt < 4; mt++)
        aab[mt] = asBase + (((wm * 64 + mt * 16 + (seg & 1) * 8 + sr) * SMS
                             + (seg >> 1) * 4) << 2);
    uint32_t bab[2];
    const uint32_t bsBase = smem_u32(Bs);
    #pragma unroll
    for (int p = 0; p < 2; p++)
        bab[p] = bsBase + (((wn * 32 + p * 16 + (seg >> 1) * 8 + sr) * SMS
                            + (seg & 1) * 4) << 2);

    float acc[4][4][4];
    #pragma unroll
    for (int mt = 0; mt < 4; mt++)
        #pragma unroll
        for (int nt = 0; nt < 4; nt++)
            #pragma unroll
            for (int r = 0; r < 4; r++) acc[mt][nt][r] = 0.f;

    float4 pa[4], pb[4];

    // prefetch tile 0
    #pragma unroll
    for (int i = 0; i < 4; i++) {
        const int row = grow + i * 32;
        pa[i] = *(const float4*)(A + (size_t)(bm + row) * DM + gf4 * 4);
        pb[i] = *(const float4*)(W + (size_t)(bn + row) * DM + gf4 * 4);
    }

    for (int t = 0; t < DM / 32; t++) {
        __syncthreads();   // previous tile fully consumed
        #pragma unroll
        for (int i = 0; i < 4; i++) {
            const int row = grow + i * 32;
            *(uint4*)&As[row * SMS + gf4 * 4] =
                make_uint4(f2tf(pa[i].x), f2tf(pa[i].y), f2tf(pa[i].z), f2tf(pa[i].w));
            *(uint4*)&Bs[row * SMS + gf4 * 4] =
                make_uint4(f2tf(pb[i].x), f2tf(pb[i].y), f2tf(pb[i].z), f2tf(pb[i].w));
        }
        __syncthreads();

        if (t + 1 < DM / 32) {
            const int k0 = (t + 1) * 32;
            #pragma unroll
            for (int i = 0; i < 4; i++) {
                const int row = grow + i * 32;
                pa[i] = *(const float4*)(A + (size_t)(bm + row) * DM + k0 + gf4 * 4);
                pb[i] = *(const float4*)(W + (size_t)(bn + row) * DM + k0 + gf4 * 4);
            }
        }

        #pragma unroll
        for (int kk = 0; kk < 4; kk++) {
            const uint32_t koff = kk * 32;   // 8 floats = 32 bytes
            uint32_t af[4][4], bf[4][2];
            #pragma unroll
            for (int mt = 0; mt < 4; mt++)
                ldsm4(af[mt][0], af[mt][1], af[mt][2], af[mt][3], aab[mt] + koff);
            ldsm4(bf[0][0], bf[0][1], bf[1][0], bf[1][1], bab[0] + koff);
            ldsm4(bf[2][0], bf[2][1], bf[3][0], bf[3][1], bab[1] + koff);
            #pragma unroll
            for (int mt = 0; mt < 4; mt++)
                #pragma unroll
                for (int nt = 0; nt < 4; nt++)
                    mma8(acc[mt][nt][0], acc[mt][nt][1], acc[mt][nt][2], acc[mt][nt][3],
                         af[mt][0], af[mt][1], af[mt][2], af[mt][3],
                         bf[nt][0], bf[nt][1]);
        }
    }

    // Epilogue
    #pragma unroll
    for (int mt = 0; mt < 4; mt++) {
        const int row = bm + wm * 64 + mt * 16 + lr;
        #pragma unroll
        for (int nt = 0; nt < 4; nt++) {
            const int col = bn + wn * 32 + nt * 8 + 2 * lk;
            const float bx = bias[col];
            const float by = bias[col + 1];
            float2 r0 = make_float2(acc[mt][nt][0] + bx, acc[mt][nt][1] + by);
            float2 r1 = make_float2(acc[mt][nt][2] + bx, acc[mt][nt][3] + by);
            if (MODE == 0) {
                *(float2*)&C[(size_t)row * DM + col]       = r0;
                *(float2*)&C[(size_t)(row + 8) * DM + col] = r1;
            } else {
                const int h_  = col >> 6;
                const int dk  = col & (HD - 1);
                const int b0_ = row >> 11;
                const int s0_ = row & (SQ - 1);
                const int b1_ = (row + 8) >> 11;
                const int s1_ = (row + 8) & (SQ - 1);
                *(float2*)&C[(((size_t)(b0_ * NH + h_) * SQ) + s0_) * HD + dk] = r0;
                *(float2*)&C[(((size_t)(b1_ * NH + h_) * SQ) + s1_) * HD + dk] = r1;
            }
        }
    }
}

// ---------------------------------------------------------------------------
// Tensor-core flash attention (causal), tf32 mma (R7 two-sync staging).
// QK^T split: qh*kh + qh*kl. V stored TRANSPOSED (VT[d][kv], stride 68) so
// PV B-fragments come from ldmatrix instead of 128 scalar LDS per tile.
// Softmax in log2 domain (ex2.approx), scale folded into scores.
// ---------------------------------------------------------------------------
#define KST 68                         // row stride (floats) for Kh/Kl/VT
#define ATTN_SMEM (3*64*KST*4)         // bytes: Kh + Kl + VT
#define SCL 0.18033688011112042f       // 0.125 * log2(e)

__global__ void __launch_bounds__(256, 1)
attn_tc_kernel(const float* __restrict__ Q, const float* __restrict__ K,
               const float* __restrict__ V, float* __restrict__ O)
{
    extern __shared__ uint32_t smem[];
    uint32_t* Kh = smem;                 // 64 x KST  (tf32 hi), rows = kv, cols = d
    uint32_t* Kl = smem + 64 * KST;      // 64 x KST  (tf32 residual)
    uint32_t* VT = smem + 2 * 64 * KST;  // 64 x KST  (tf32), rows = d, cols = kv

    const int tid  = threadIdx.x;
    const int lane = tid & 31;
    const int w    = tid >> 5;           // warp 0..7
    const int lr   = lane >> 2;          // group id 0..7
    const int lk   = lane & 3;           // thread-in-group 0..3
    const int seg  = lane >> 3;
    const int sr   = lane & 7;

    const int qblk = (SQ / 128 - 1) - blockIdx.x;   // reversed: long blocks first
    const int h    = blockIdx.y;
    const int b    = blockIdx.z;
    const int qbase = qblk * 128;

    const size_t headbase = (size_t)(b * NH + h) * SQ * HD;
    const float* Qg = Q + headbase;
    const float* Kg = K + headbase;
    const float* Vg = V + headbase;

    // ldmatrix per-lane base addrs: K tiles (rows=kv over nt, col=d) and
    // VT tiles (rows=d over nt, col=kv) share the same formula (stride KST).
    uint32_t khb[4], klb[4], vtb[4];
    {
        const uint32_t sBase = smem_u32(smem);
        #pragma unroll
        for (int p = 0; p < 4; p++) {
            const uint32_t off = (((p * 16 + (seg >> 1) * 8 + sr) * KST
                                   + (seg & 1) * 4) << 2);
            khb[p] = sBase + off;
            klb[p] = sBase + (64 * KST * 4) + off;
            vtb[p] = sBase + (2 * 64 * KST * 4) + off;
        }
    }

    // --- Q fragments (persistent, single tf32), rows w*16 + {lr, lr+8} ---
    const int r0 = qbase + w * 16 + lr;
    uint32_t qh[8][4];
    #pragma unroll
    for (int kk = 0; kk < 8; kk++) {
        qh[kk][0] = f2tf(Qg[(size_t)r0 * HD + kk * 8 + lk]);
        qh[kk][1] = f2tf(Qg[(size_t)(r0 + 8) * HD + kk * 8 + lk]);
        qh[kk][2] = f2tf(Qg[(size_t)r0 * HD + kk * 8 + 4 + lk]);
        qh[kk][3] = f2tf(Qg[(size_t)(r0 + 8) * HD + kk * 8 + 4 + lk]);
    }

    float oacc[8][4];
    #pragma unroll
    for (int nt = 0; nt < 8; nt++)
        #pragma unroll
        for (int r = 0; r < 4; r++) oacc[nt][r] = 0.f;

    float m0 = -1e30f, m1 = -1e30f, l0 = 0.f, l1 = 0.f;

    const int ntiles = 2 * qblk + 2;

    // K staging slot (row-major): row = tid>>4 (+16 per i), 4 floats at stc4
    const int strow = tid >> 4;
    const int stc4  = (tid & 15) * 4;
    // V staging slot (column-major): d = tid&63, kv base = (tid>>6)*4 (+16 per i)
    const int vd   = tid & 63;
    const int vkv  = (tid >> 6) * 4;

    // prefetch tile 0 into registers
    float4 pk[4];
    float  pv[4][4];
    #pragma unroll
    for (int i = 0; i < 4; i++) {
        pk[i] = *(const float4*)&Kg[(size_t)(strow + i * 16) * HD + stc4];
        #pragma unroll
        for (int j = 0; j < 4; j++)
            pv[i][j] = Vg[(size_t)(vkv + i * 16 + j) * HD + vd];
    }

    for (int kt = 0; kt < ntiles; kt++) {
        __syncthreads();   // previous tile fully consumed
        // stage K (hi+lo, row-major) and V (transposed) into smem
        #pragma unroll
        for (int i = 0; i < 4; i++) {
            const int row = strow + i * 16;
            uint32_t hx = f2tf(pk[i].x), hy = f2tf(pk[i].y),
                     hz = f2tf(pk[i].z), hw = f2tf(pk[i].w);
            *(uint4*)&Kh[row * KST + stc4] = make_uint4(hx, hy, hz, hw);
            *(uint4*)&Kl[row * KST + stc4] = make_uint4(
                f2tf(pk[i].x - __uint_as_float(hx)), f2tf(pk[i].y - __uint_as_float(hy)),
                f2tf(pk[i].z - __uint_as_float(hz)), f2tf(pk[i].w - __uint_as_float(hw)));
            *(uint4*)&VT[vd * KST + vkv + i * 16] = make_uint4(
                f2tf(pv[i][0]), f2tf(pv[i][1]), f2tf(pv[i][2]), f2tf(pv[i][3]));
        }
        __syncthreads();

        // prefetch next tile (covered by compute below)
        if (kt + 1 < ntiles) {
            const int base = (kt + 1) * 64;
            #pragma unroll
            for (int i = 0; i < 4; i++) {
                pk[i] = *(const float4*)&Kg[(size_t)(base + strow + i * 16) * HD + stc4];
                #pragma unroll
                for (int j = 0; j < 4; j++)
                    pv[i][j] = Vg[(size_t)(base + vkv + i * 16 + j) * HD + vd];
            }
        }

        // --- S = Q K^T (qh*kh + qh*kl) ---
        float sacc[8][4];
        #pragma unroll
        for (int nt = 0; nt < 8; nt++)
            #pragma unroll
            for (int r = 0; r < 4; r++) sacc[nt][r] = 0.f;

        #pragma unroll
        for (int kk = 0; kk < 8; kk++) {
            const uint32_t koff = kk * 32;
            uint32_t kb[8][2], lb[8][2];
            #pragma unroll
            for (int p = 0; p < 4; p++) {
                ldsm4(kb[2*p][0], kb[2*p][1], kb[2*p+1][0], kb[2*p+1][1], khb[p] + koff);
                ldsm4(lb[2*p][0], lb[2*p][1], lb[2*p+1][0], lb[2*p+1][1], klb[p] + koff);
            }
            #pragma unroll
            for (int nt = 0; nt < 8; nt++) {
                mma8(sacc[nt][0], sacc[nt][1], sacc[nt][2], sacc[nt][3],
                     qh[kk][0], qh[kk][1], qh[kk][2], qh[kk][3], kb[nt][0], kb[nt][1]);
                mma8(sacc[nt][0], sacc[nt][1], sacc[nt][2], sacc[nt][3],
                     qh[kk][0], qh[kk][1], qh[kk][2], qh[kk][3], lb[nt][0], lb[nt][1]);
            }
        }

        // --- scale (log2 domain) + causal mask ---
        const bool may_mask = (kt * 64 + 63 > qbase);
        #pragma unroll
        for (int nt = 0; nt < 8; nt++) {
            const int c = kt * 64 + nt * 8 + 2 * lk;
            #pragma unroll
            for (int r = 0; r < 4; r++) sacc[nt][r] *= SCL;
            if (may_mask) {
                if (c     > r0)     sacc[nt][0] = -1e30f;
                if (c + 1 > r0)     sacc[nt][1] = -1e30f;
                if (c     > r0 + 8) sacc[nt][2] = -1e30f;
                if (c + 1 > r0 + 8) sacc[nt][3] = -1e30f;
            }
        }

        // --- online softmax (rows r0 and r0+8), base-2 ---
        float tm0 = -1e30f, tm1 = -1e30f;
        #pragma unroll
        for (int nt = 0; nt < 8; nt++) {
            tm0 = fmaxf(tm0, fmaxf(sacc[nt][0], sacc[nt][1]));
            tm1 = fmaxf(tm1, fmaxf(sacc[nt][2], sacc[nt][3]));
        }
        tm0 = fmaxf(tm0, __shfl_xor_sync(0xffffffff, tm0, 1));
        tm0 = fmaxf(tm0, __shfl_xor_sync(0xffffffff, tm0, 2));
        tm1 = fmaxf(tm1, __shfl_xor_sync(0xffffffff, tm1, 1));
        tm1 = fmaxf(tm1, __shfl_xor_sync(0xffffffff, tm1, 2));

        const float mn0 = fmaxf(m0, tm0);
        const float mn1 = fmaxf(m1, tm1);
        const float cor0 = ex2f(m0 - mn0);
        const float cor1 = ex2f(m1 - mn1);
        m0 = mn0; m1 = mn1;

        float sum0 = 0.f, sum1 = 0.f;
        #pragma unroll
        for (int nt = 0; nt < 8; nt++) {
            sacc[nt][0] = ex2f(sacc[nt][0] - m0);
            sacc[nt][1] = ex2f(sacc[nt][1] - m0);
            sacc[nt][2] = ex2f(sacc[nt][2] - m1);
            sacc[nt][3] = ex2f(sacc[nt][3] - m1);
            sum0 += sacc[nt][0] + sacc[nt][1];
            sum1 += sacc[nt][2] + sacc[nt][3];
        }
        sum0 += __shfl_xor_sync(0xffffffff, sum0, 1);
        sum0 += __shfl_xor_sync(0xffffffff, sum0, 2);
        sum1 += __shfl_xor_sync(0xffffffff, sum1, 1);
        sum1 += __shfl_xor_sync(0xffffffff, sum1, 2);
        l0 = l0 * cor0 + sum0;
        l1 = l1 * cor1 + sum1;

        #pragma unroll
        for (int nt = 0; nt < 8; nt++) {
            oacc[nt][0] *= cor0; oacc[nt][1] *= cor0;
            oacc[nt][2] *= cor1; oacc[nt][3] *= cor1;
        }

        // --- O += P V (V B-fragments via ldmatrix on VT) ---
        const int s0 = (lane & ~3) | (lk >> 1);   // src lane for cols lk
        const int s2 = s0 + 2;                    // src lane for cols lk+4
        const int par = lk & 1;
        #pragma unroll
        for (int kk = 0; kk < 8; kk++) {
            // rebuild A-fragment of P for this 8-key chunk via in-quad shuffles
            float v00 = __shfl_sync(0xffffffff, sacc[kk][0], s0);
            float v01 = __shfl_sync(0xffffffff, sacc[kk][1], s0);
            float v20 = __shfl_sync(0xffffffff, sacc[kk][0], s2);
            float v21 = __shfl_sync(0xffffffff, sacc[kk][1], s2);
            float v10 = __shfl_sync(0xffffffff, sacc[kk][2], s0);
            float v11 = __shfl_sync(0xffffffff, sacc[kk][3], s0);
            float v30 = __shfl_sync(0xffffffff, sacc[kk][2], s2);
            float v31 = __shfl_sync(0xffffffff, sacc[kk][3], s2);
            uint32_t a0 = f2tf(par ? v01 : v00);
            uint32_t a1 = f2tf(par ? v11 : v10);
            uint32_t a2 = f2tf(par ? v21 : v20);
            uint32_t a3 = f2tf(par ? v31 : v30);

            const uint32_t koff = kk * 32;       // advance kv within VT rows
            uint32_t vb[8][2];
            #pragma unroll
            for (int p = 0; p < 4; p++)
                ldsm4(vb[2*p][0], vb[2*p][1], vb[2*p+1][0], vb[2*p+1][1], vtb[p] + koff);

            #pragma unroll
            for (int nt = 0; nt < 8; nt++)
                mma8(oacc[nt][0], oacc[nt][1], oacc[nt][2], oacc[nt][3],
                     a0, a1, a2, a3, vb[nt][0], vb[nt][1]);
        }
    }

    // --- write O: [b, s, h*64 + d] ---
    const float inv0 = 1.f / l0;
    const float inv1 = 1.f / l1;
    float* Ob0 = O + ((size_t)b * SQ + r0) * DM + h * HD;
    float* Ob1 = O + ((size_t)b * SQ + r0 + 8) * DM + h * HD;
    #pragma unroll
    for (int nt = 0; nt < 8; nt++) {
        const int c = nt * 8 + 2 * lk;
        *(float2*)&Ob0[c] = make_float2(oacc[nt][0] * inv0, oacc[nt][1] * inv0);
        *(float2*)&Ob1[c] = make_float2(oacc[nt][2] * inv1, oacc[nt][3] * inv1);
    }
}

// ---------------------------------------------------------------------------
// Launch: fused QKV projection GEMM -> TC flash attention -> output GEMM
// Inputs (metadata order): query, key, value, mask(unused; tril causal),
//   w_q, b_q, w_k, b_k, w_v, b_v, w_out, b_out
// ---------------------------------------------------------------------------
extern "C" void kernel_launch(void* const* d_in, const int* in_sizes, int n_in,
                              void* d_out, int out_size)
{
    const float* query = (const float*)d_in[0];
    const float* key   = (const float*)d_in[1];
    const float* value = (const float*)d_in[2];
    const float* w_q   = (const float*)d_in[4];
    const float* b_q   = (const float*)d_in[5];
    const float* w_k   = (const float*)d_in[6];
    const float* b_k   = (const float*)d_in[7];
    const float* w_v   = (const float*)d_in[8];
    const float* b_v   = (const float*)d_in[9];
    const float* w_out = (const float*)d_in[10];
    const float* b_out = (const float*)d_in[11];

    float *Qp, *Kp, *Vp, *Op;
    cudaGetSymbolAddress((void**)&Qp, g_Q);
    cudaGetSymbolAddress((void**)&Kp, g_K);
    cudaGetSymbolAddress((void**)&Vp, g_V);
    cudaGetSymbolAddress((void**)&Op, g_O);

    cudaFuncSetAttribute(attn_tc_kernel,
                         cudaFuncAttributeMaxDynamicSharedMemorySize, ATTN_SMEM);

    // fused Q/K/V projections: gridDim.z selects operand set
    dim3 pgrid(DM / 128, MT / 128, 3);   // (8, 32, 3)
    gemm_tc_kernel<1><<<pgrid, 256>>>(
        query, key, value, w_q, w_k, w_v, b_q, b_k, b_v, Qp, Kp, Vp);

    attn_tc_kernel<<<dim3(SQ / 128, NH, NB), 256, ATTN_SMEM>>>(Qp, Kp, Vp, Op);

    dim3 ogrid(DM / 128, MT / 128, 1);
    gemm_tc_kernel<0><<<ogrid, 256>>>(
        Op, Op, Op, w_out, w_out, w_out, b_out, b_out, b_out,
        (float*)d_out, (float*)d_out, (float*)d_out);
}

// round 11
// speedup vs baseline: 1.6805x; 1.0718x over previous
#include <cuda_runtime.h>
#include <cstdint>

// Problem constants
#define SQ   2048          // sequence length
#define DM   1024          // model dim
#define NH   16            // heads
#define HD   64            // head dim
#define NB   2             // batch
#define MT   (NB*SQ)       // 4096 rows total

// Scratch (device globals; no allocation allowed in kernel_launch)
__device__ float g_Q[NB*NH*SQ*HD];   // [B,H,S,HD]
__device__ float g_K[NB*NH*SQ*HD];
__device__ float g_V[NB*NH*SQ*HD];
__device__ float g_O[MT*DM];         // [B,S,D] attention output (pre out-proj)

// ---------------------------------------------------------------------------
// helpers
// ---------------------------------------------------------------------------
__device__ __forceinline__ uint32_t f2tf(float f) {
    uint32_t u;
    asm("cvt.rna.tf32.f32 %0, %1;" : "=r"(u) : "f"(f));
    return u;
}

__device__ __forceinline__ float ex2f(float x) {
    float r;
    asm("ex2.approx.ftz.f32 %0, %1;" : "=f"(r) : "f"(x));
    return r;
}

__device__ __forceinline__ void mma8(float& c0, float& c1, float& c2, float& c3,
                                     uint32_t a0, uint32_t a1, uint32_t a2, uint32_t a3,
                                     uint32_t b0, uint32_t b1) {
    asm("mma.sync.aligned.m16n8k8.row.col.f32.tf32.tf32.f32 "
        "{%0,%1,%2,%3}, {%4,%5,%6,%7}, {%8,%9}, {%0,%1,%2,%3};"
        : "+f"(c0), "+f"(c1), "+f"(c2), "+f"(c3)
        : "r"(a0), "r"(a1), "r"(a2), "r"(a3), "r"(b0), "r"(b1));
}

// ldmatrix x4: four 8x4 b32 tiles; lane l gets, per tile, element (l>>2, l&3).
__device__ __forceinline__ void ldsm4(uint32_t& r0, uint32_t& r1,
                                      uint32_t& r2, uint32_t& r3, uint32_t addr) {
    asm volatile("ldmatrix.sync.aligned.m8n8.x4.shared.b16 {%0,%1,%2,%3}, [%4];"
                 : "=r"(r0), "=r"(r1), "=r"(r2), "=r"(r3) : "r"(addr));
}

__device__ __forceinline__ uint32_t smem_u32(const void* p) {
    return (uint32_t)__cvta_generic_to_shared(p);
}

// ---------------------------------------------------------------------------
// tf32 tensor-core GEMM, 2 blocks/SM: C = A[M,K]@W[N,K]^T + bias
//   MODE 0: C row-major [M,N]     (launched gridDim.z = 1)
//   MODE 1: C head-split          (launched gridDim.z = 3: fused Q/K/V)
// 128x128 block, BK=32, 8 warps (2Mx4N), warp tile 64x32, ldmatrix fragments.
// NO register prefetch: plain sync/stage/sync/compute; the co-resident block
// hides staging latency (that's what occupancy 2 buys).
// ---------------------------------------------------------------------------
#define SMS 36   // smem row stride in floats (4*row+k bijective mod 32)

template<int MODE>
__global__ void __launch_bounds__(256, 2)
gemm_tc_kernel(const float* A0, const float* A1, const float* A2,
               const float* W0, const float* W1, const float* W2,
               const float* bi0, const float* bi1, const float* bi2,
               float* C0, float* C1, float* C2)
{
    __shared__ uint32_t As[128 * SMS];
    __shared__ uint32_t Bs[128 * SMS];

    const int z = blockIdx.z;
    const float* A    = (z == 0) ? A0  : (z == 1) ? A1  : A2;
    const float* W    = (z == 0) ? W0  : (z == 1) ? W1  : W2;
    const float* bias = (z == 0) ? bi0 : (z == 1) ? bi1 : bi2;
    float*       C    = (z == 0) ? C0  : (z == 1) ? C1  : C2;

    const int tid  = threadIdx.x;
    const int lane = tid & 31;
    const int wid  = tid >> 5;
    const int wm   = wid >> 2;        // 0..1  (M warp)
    const int wn   = wid & 3;         // 0..3  (N warp)
    const int lr   = lane >> 2;       // 0..7
    const int lk   = lane & 3;        // 0..3
    const int seg  = lane >> 3;       // ldmatrix tile segment 0..3
    const int sr   = lane & 7;        // row within tile segment
    const int bm   = blockIdx.y * 128;
    const int bn   = blockIdx.x * 128;

    const int grow = tid >> 3;        // base row (0..31), +32 per i
    const int gf4  = tid & 7;         // float4 index within 32-float k-chunk

    // ldmatrix per-lane base addresses (bytes)
    uint32_t aab[4];
    const uint32_t asBase = smem_u32(As);
    #pragma unroll
    for (int mt = 0; mt < 4; mt++)
        aab[mt] = asBase + (((wm * 64 + mt * 16 + (seg & 1) * 8 + sr) * SMS
                             + (seg >> 1) * 4) << 2);
    uint32_t bab[2];
    const uint32_t bsBase = smem_u32(Bs);
    #pragma unroll
    for (int p = 0; p < 2; p++)
        bab[p] = bsBase + (((wn * 32 + p * 16 + (seg >> 1) * 8 + sr) * SMS
                            + (seg & 1) * 4) << 2);

    float acc[4][4][4];
    #pragma unroll
    for (int mt = 0; mt < 4; mt++)
        #pragma unroll
        for (int nt = 0; nt < 4; nt++)
            #pragma unroll
            for (int r = 0; r < 4; r++) acc[mt][nt][r] = 0.f;

    const float* Ab = A + (size_t)bm * DM + gf4 * 4;
    const float* Wb = W + (size_t)bn * DM + gf4 * 4;

    for (int t = 0; t < DM / 32; t++) {
        const int k0 = t * 32;
        __syncthreads();   // previous tile fully consumed
        #pragma unroll
        for (int i = 0; i < 4; i++) {
            const int row = grow + i * 32;
            float4 a = *(const float4*)(Ab + (size_t)row * DM + k0);
            float4 w = *(const float4*)(Wb + (size_t)row * DM + k0);
            *(uint4*)&As[row * SMS + gf4 * 4] =
                make_uint4(f2tf(a.x), f2tf(a.y), f2tf(a.z), f2tf(a.w));
            *(uint4*)&Bs[row * SMS + gf4 * 4] =
                make_uint4(f2tf(w.x), f2tf(w.y), f2tf(w.z), f2tf(w.w));
        }
        __syncthreads();

        #pragma unroll
        for (int kk = 0; kk < 4; kk++) {
            const uint32_t koff = kk * 32;   // 8 floats = 32 bytes
            uint32_t af[4][4], bf[4][2];
            #pragma unroll
            for (int mt = 0; mt < 4; mt++)
                ldsm4(af[mt][0], af[mt][1], af[mt][2], af[mt][3], aab[mt] + koff);
            ldsm4(bf[0][0], bf[0][1], bf[1][0], bf[1][1], bab[0] + koff);
            ldsm4(bf[2][0], bf[2][1], bf[3][0], bf[3][1], bab[1] + koff);
            #pragma unroll
            for (int mt = 0; mt < 4; mt++)
                #pragma unroll
                for (int nt = 0; nt < 4; nt++)
                    mma8(acc[mt][nt][0], acc[mt][nt][1], acc[mt][nt][2], acc[mt][nt][3],
                         af[mt][0], af[mt][1], af[mt][2], af[mt][3],
                         bf[nt][0], bf[nt][1]);
        }
    }

    // Epilogue
    #pragma unroll
    for (int mt = 0; mt < 4; mt++) {
        const int row = bm + wm * 64 + mt * 16 + lr;
        #pragma unroll
        for (int nt = 0; nt < 4; nt++) {
            const int col = bn + wn * 32 + nt * 8 + 2 * lk;
            const float bx = bias[col];
            const float by = bias[col + 1];
            float2 r0 = make_float2(acc[mt][nt][0] + bx, acc[mt][nt][1] + by);
            float2 r1 = make_float2(acc[mt][nt][2] + bx, acc[mt][nt][3] + by);
            if (MODE == 0) {
                *(float2*)&C[(size_t)row * DM + col]       = r0;
                *(float2*)&C[(size_t)(row + 8) * DM + col] = r1;
            } else {
                const int h_  = col >> 6;
                const int dk  = col & (HD - 1);
                const int b0_ = row >> 11;
                const int s0_ = row & (SQ - 1);
                const int b1_ = (row + 8) >> 11;
                const int s1_ = (row + 8) & (SQ - 1);
                *(float2*)&C[(((size_t)(b0_ * NH + h_) * SQ) + s0_) * HD + dk] = r0;
                *(float2*)&C[(((size_t)(b1_ * NH + h_) * SQ) + s1_) * HD + dk] = r1;
            }
        }
    }
}

// ---------------------------------------------------------------------------
// Tensor-core flash attention (causal), tf32 mma (unchanged from R10).
// QK^T split: qh*kh + qh*kl. V stored TRANSPOSED (VT[d][kv], stride 68) so
// PV B-fragments come from ldmatrix. Softmax in log2 domain (ex2.approx).
// ---------------------------------------------------------------------------
#define KST 68                         // row stride (floats) for Kh/Kl/VT
#define ATTN_SMEM (3*64*KST*4)         // bytes: Kh + Kl + VT
#define SCL 0.18033688011112042f       // 0.125 * log2(e)

__global__ void __launch_bounds__(256, 1)
attn_tc_kernel(const float* __restrict__ Q, const float* __restrict__ K,
               const float* __restrict__ V, float* __restrict__ O)
{
    extern __shared__ uint32_t smem[];
    uint32_t* Kh = smem;                 // 64 x KST  (tf32 hi), rows = kv, cols = d
    uint32_t* Kl = smem + 64 * KST;      // 64 x KST  (tf32 residual)
    uint32_t* VT = smem + 2 * 64 * KST;  // 64 x KST  (tf32), rows = d, cols = kv

    const int tid  = threadIdx.x;
    const int lane = tid & 31;
    const int w    = tid >> 5;           // warp 0..7
    const int lr   = lane >> 2;          // group id 0..7
    const int lk   = lane & 3;           // thread-in-group 0..3
    const int seg  = lane >> 3;
    const int sr   = lane & 7;

    const int qblk = (SQ / 128 - 1) - blockIdx.x;   // reversed: long blocks first
    const int h    = blockIdx.y;
    const int b    = blockIdx.z;
    const int qbase = qblk * 128;

    const size_t headbase = (size_t)(b * NH + h) * SQ * HD;
    const float* Qg = Q + headbase;
    const float* Kg = K + headbase;
    const float* Vg = V + headbase;

    // ldmatrix per-lane base addrs: K tiles (rows=kv) and VT tiles (rows=d).
    uint32_t khb[4], klb[4], vtb[4];
    {
        const uint32_t sBase = smem_u32(smem);
        #pragma unroll
        for (int p = 0; p < 4; p++) {
            const uint32_t off = (((p * 16 + (seg >> 1) * 8 + sr) * KST
                                   + (seg & 1) * 4) << 2);
            khb[p] = sBase + off;
            klb[p] = sBase + (64 * KST * 4) + off;
            vtb[p] = sBase + (2 * 64 * KST * 4) + off;
        }
    }

    // --- Q fragments (persistent, single tf32), rows w*16 + {lr, lr+8} ---
    const int r0 = qbase + w * 16 + lr;
    uint32_t qh[8][4];
    #pragma unroll
    for (int kk = 0; kk < 8; kk++) {
        qh[kk][0] = f2tf(Qg[(size_t)r0 * HD + kk * 8 + lk]);
        qh[kk][1] = f2tf(Qg[(size_t)(r0 + 8) * HD + kk * 8 + lk]);
        qh[kk][2] = f2tf(Qg[(size_t)r0 * HD + kk * 8 + 4 + lk]);
        qh[kk][3] = f2tf(Qg[(size_t)(r0 + 8) * HD + kk * 8 + 4 + lk]);
    }

    float oacc[8][4];
    #pragma unroll
    for (int nt = 0; nt < 8; nt++)
        #pragma unroll
        for (int r = 0; r < 4; r++) oacc[nt][r] = 0.f;

    float m0 = -1e30f, m1 = -1e30f, l0 = 0.f, l1 = 0.f;

    const int ntiles = 2 * qblk + 2;

    // K staging slot (row-major): row = tid>>4 (+16 per i), 4 floats at stc4
    const int strow = tid >> 4;
    const int stc4  = (tid & 15) * 4;
    // V staging slot (column-major): d = tid&63, kv base = (tid>>6)*4 (+16 per i)
    const int vd   = tid & 63;
    const int vkv  = (tid >> 6) * 4;

    // prefetch tile 0 into registers
    float4 pk[4];
    float  pv[4][4];
    #pragma unroll
    for (int i = 0; i < 4; i++) {
        pk[i] = *(const float4*)&Kg[(size_t)(strow + i * 16) * HD + stc4];
        #pragma unroll
        for (int j = 0; j < 4; j++)
            pv[i][j] = Vg[(size_t)(vkv + i * 16 + j) * HD + vd];
    }

    for (int kt = 0; kt < ntiles; kt++) {
        __syncthreads();   // previous tile fully consumed
        // stage K (hi+lo, row-major) and V (transposed) into smem
        #pragma unroll
        for (int i = 0; i < 4; i++) {
            const int row = strow + i * 16;
            uint32_t hx = f2tf(pk[i].x), hy = f2tf(pk[i].y),
                     hz = f2tf(pk[i].z), hw = f2tf(pk[i].w);
            *(uint4*)&Kh[row * KST + stc4] = make_uint4(hx, hy, hz, hw);
            *(uint4*)&Kl[row * KST + stc4] = make_uint4(
                f2tf(pk[i].x - __uint_as_float(hx)), f2tf(pk[i].y - __uint_as_float(hy)),
                f2tf(pk[i].z - __uint_as_float(hz)), f2tf(pk[i].w - __uint_as_float(hw)));
            *(uint4*)&VT[vd * KST + vkv + i * 16] = make_uint4(
                f2tf(pv[i][0]), f2tf(pv[i][1]), f2tf(pv[i][2]), f2tf(pv[i][3]));
        }
        __syncthreads();

        // prefetch next tile (covered by compute below)
        if (kt + 1 < ntiles) {
            const int base = (kt + 1) * 64;
            #pragma unroll
            for (int i = 0; i < 4; i++) {
                pk[i] = *(const float4*)&Kg[(size_t)(base + strow + i * 16) * HD + stc4];
                #pragma unroll
                for (int j = 0; j < 4; j++)
                    pv[i][j] = Vg[(size_t)(base + vkv + i * 16 + j) * HD + vd];
            }
        }

        // --- S = Q K^T (qh*kh + qh*kl) ---
        float sacc[8][4];
        #pragma unroll
        for (int nt = 0; nt < 8; nt++)
            #pragma unroll
            for (int r = 0; r < 4; r++) sacc[nt][r] = 0.f;

        #pragma unroll
        for (int kk = 0; kk < 8; kk++) {
            const uint32_t koff = kk * 32;
            uint32_t kb[8][2], lb[8][2];
            #pragma unroll
            for (int p = 0; p < 4; p++) {
                ldsm4(kb[2*p][0], kb[2*p][1], kb[2*p+1][0], kb[2*p+1][1], khb[p] + koff);
                ldsm4(lb[2*p][0], lb[2*p][1], lb[2*p+1][0], lb[2*p+1][1], klb[p] + koff);
            }
            #pragma unroll
            for (int nt = 0; nt < 8; nt++) {
                mma8(sacc[nt][0], sacc[nt][1], sacc[nt][2], sacc[nt][3],
                     qh[kk][0], qh[kk][1], qh[kk][2], qh[kk][3], kb[nt][0], kb[nt][1]);
                mma8(sacc[nt][0], sacc[nt][1], sacc[nt][2], sacc[nt][3],
                     qh[kk][0], qh[kk][1], qh[kk][2], qh[kk][3], lb[nt][0], lb[nt][1]);
            }
        }

        // --- scale (log2 domain) + causal mask ---
        const bool may_mask = (kt * 64 + 63 > qbase);
        #pragma unroll
        for (int nt = 0; nt < 8; nt++) {
            const int c = kt * 64 + nt * 8 + 2 * lk;
            #pragma unroll
            for (int r = 0; r < 4; r++) sacc[nt][r] *= SCL;
            if (may_mask) {
                if (c     > r0)     sacc[nt][0] = -1e30f;
                if (c + 1 > r0)     sacc[nt][1] = -1e30f;
                if (c     > r0 + 8) sacc[nt][2] = -1e30f;
                if (c + 1 > r0 + 8) sacc[nt][3] = -1e30f;
            }
        }

        // --- online softmax (rows r0 and r0+8), base-2 ---
        float tm0 = -1e30f, tm1 = -1e30f;
        #pragma unroll
        for (int nt = 0; nt < 8; nt++) {
            tm0 = fmaxf(tm0, fmaxf(sacc[nt][0], sacc[nt][1]));
            tm1 = fmaxf(tm1, fmaxf(sacc[nt][2], sacc[nt][3]));
        }
        tm0 = fmaxf(tm0, __shfl_xor_sync(0xffffffff, tm0, 1));
        tm0 = fmaxf(tm0, __shfl_xor_sync(0xffffffff, tm0, 2));
        tm1 = fmaxf(tm1, __shfl_xor_sync(0xffffffff, tm1, 1));
        tm1 = fmaxf(tm1, __shfl_xor_sync(0xffffffff, tm1, 2));

        const float mn0 = fmaxf(m0, tm0);
        const float mn1 = fmaxf(m1, tm1);
        const float cor0 = ex2f(m0 - mn0);
        const float cor1 = ex2f(m1 - mn1);
        m0 = mn0; m1 = mn1;

        float sum0 = 0.f, sum1 = 0.f;
        #pragma unroll
        for (int nt = 0; nt < 8; nt++) {
            sacc[nt][0] = ex2f(sacc[nt][0] - m0);
            sacc[nt][1] = ex2f(sacc[nt][1] - m0);
            sacc[nt][2] = ex2f(sacc[nt][2] - m1);
            sacc[nt][3] = ex2f(sacc[nt][3] - m1);
            sum0 += sacc[nt][0] + sacc[nt][1];
            sum1 += sacc[nt][2] + sacc[nt][3];
        }
        sum0 += __shfl_xor_sync(0xffffffff, sum0, 1);
        sum0 += __shfl_xor_sync(0xffffffff, sum0, 2);
        sum1 += __shfl_xor_sync(0xffffffff, sum1, 1);
        sum1 += __shfl_xor_sync(0xffffffff, sum1, 2);
        l0 = l0 * cor0 + sum0;
        l1 = l1 * cor1 + sum1;

        #pragma unroll
        for (int nt = 0; nt < 8; nt++) {
            oacc[nt][0] *= cor0; oacc[nt][1] *= cor0;
            oacc[nt][2] *= cor1; oacc[nt][3] *= cor1;
        }

        // --- O += P V (V B-fragments via ldmatrix on VT) ---
        const int s0 = (lane & ~3) | (lk >> 1);   // src lane for cols lk
        const int s2 = s0 + 2;                    // src lane for cols lk+4
        const int par = lk & 1;
        #pragma unroll
        for (int kk = 0; kk < 8; kk++) {
            float v00 = __shfl_sync(0xffffffff, sacc[kk][0], s0);
            float v01 = __shfl_sync(0xffffffff, sacc[kk][1], s0);
            float v20 = __shfl_sync(0xffffffff, sacc[kk][0], s2);
            float v21 = __shfl_sync(0xffffffff, sacc[kk][1], s2);
            float v10 = __shfl_sync(0xffffffff, sacc[kk][2], s0);
            float v11 = __shfl_sync(0xffffffff, sacc[kk][3], s0);
            float v30 = __shfl_sync(0xffffffff, sacc[kk][2], s2);
            float v31 = __shfl_sync(0xffffffff, sacc[kk][3], s2);
            uint32_t a0 = f2tf(par ? v01 : v00);
            uint32_t a1 = f2tf(par ? v11 : v10);
            uint32_t a2 = f2tf(par ? v21 : v20);
            uint32_t a3 = f2tf(par ? v31 : v30);

            const uint32_t koff = kk * 32;       // advance kv within VT rows
            uint32_t vb[8][2];
            #pragma unroll
            for (int p = 0; p < 4; p++)
                ldsm4(vb[2*p][0], vb[2*p][1], vb[2*p+1][0], vb[2*p+1][1], vtb[p] + koff);

            #pragma unroll
            for (int nt = 0; nt < 8; nt++)
                mma8(oacc[nt][0], oacc[nt][1], oacc[nt][2], oacc[nt][3],
                     a0, a1, a2, a3, vb[nt][0], vb[nt][1]);
        }
    }

    // --- write O: [b, s, h*64 + d] ---
    const float inv0 = 1.f / l0;
    const float inv1 = 1.f / l1;
    float* Ob0 = O + ((size_t)b * SQ + r0) * DM + h * HD;
    float* Ob1 = O + ((size_t)b * SQ + r0 + 8) * DM + h * HD;
    #pragma unroll
    for (int nt = 0; nt < 8; nt++) {
        const int c = nt * 8 + 2 * lk;
        *(float2*)&Ob0[c] = make_float2(oacc[nt][0] * inv0, oacc[nt][1] * inv0);
        *(float2*)&Ob1[c] = make_float2(oacc[nt][2] * inv1, oacc[nt][3] * inv1);
    }
}

// ---------------------------------------------------------------------------
// Launch: fused QKV projection GEMM -> TC flash attention -> output GEMM
// Inputs (metadata order): query, key, value, mask(unused; tril causal),
//   w_q, b_q, w_k, b_k, w_v, b_v, w_out, b_out
// ---------------------------------------------------------------------------
extern "C" void kernel_launch(void* const* d_in, const int* in_sizes, int n_in,
                              void* d_out, int out_size)
{
    const float* query = (const float*)d_in[0];
    const float* key   = (const float*)d_in[1];
    const float* value = (const float*)d_in[2];
    const float* w_q   = (const float*)d_in[4];
    const float* b_q   = (const float*)d_in[5];
    const float* w_k   = (const float*)d_in[6];
    const float* b_k   = (const float*)d_in[7];
    const float* w_v   = (const float*)d_in[8];
    const float* b_v   = (const float*)d_in[9];
    const float* w_out = (const float*)d_in[10];
    const float* b_out = (const float*)d_in[11];

    float *Qp, *Kp, *Vp, *Op;
    cudaGetSymbolAddress((void**)&Qp, g_Q);
    cudaGetSymbolAddress((void**)&Kp, g_K);
    cudaGetSymbolAddress((void**)&Vp, g_V);
    cudaGetSymbolAddress((void**)&Op, g_O);

    cudaFuncSetAttribute(attn_tc_kernel,
                         cudaFuncAttributeMaxDynamicSharedMemorySize, ATTN_SMEM);

    // fused Q/K/V projections: gridDim.z selects operand set
    dim3 pgrid(DM / 128, MT / 128, 3);   // (8, 32, 3)
    gemm_tc_kernel<1><<<pgrid, 256>>>(
        query, key, value, w_q, w_k, w_v, b_q, b_k, b_v, Qp, Kp, Vp);

    attn_tc_kernel<<<dim3(SQ / 128, NH, NB), 256, ATTN_SMEM>>>(Qp, Kp, Vp, Op);

    dim3 ogrid(DM / 128, MT / 128, 1);
    gemm_tc_kernel<0><<<ogrid, 256>>>(
        Op, Op, Op, w_out, w_out, w_out, b_out, b_out, b_out,
        (float*)d_out, (float*)d_out, (float*)d_out);
}